// round 6
// baseline (speedup 1.0000x reference)
#include <cuda_runtime.h>
#include <cuda_bf16.h>
#include <cstdint>

#define TPB  256
#define GRID 148

// ---- dynamic shared memory layout (bytes) ----
// h1 tiles: 128 rows x 128 bf16, padded row stride 272 B (conflict-free ldmatrix)
#define H1_STRIDE 272
#define H1A_OFF   0
#define H1B_OFF   34816                    // 128*272
#define PA_OFF    69632                    // 8 warps x 128 rows x f32   (4096)
#define PB_OFF    73728                    // 8 warps x 3 ch x 128 x f32 (12288)
#define SMEM_TOTAL 86016

static __device__ __forceinline__ uint32_t smem_u32(const void* p) {
    uint32_t a;
    asm("{ .reg .u64 t; cvta.to.shared.u64 t, %1; cvt.u32.u64 %0, t; }" : "=r"(a) : "l"(p));
    return a;
}

static __device__ __forceinline__ uint32_t pack_bf16(float a, float b) {
    __nv_bfloat162 t = __floats2bfloat162_rn(a, b);
    return *reinterpret_cast<uint32_t*>(&t);
}

static __device__ __forceinline__ void ldsm_x4(uint32_t a[4], uint32_t addr) {
    asm volatile("ldmatrix.sync.aligned.m8n8.x4.shared.b16 {%0,%1,%2,%3}, [%4];"
                 : "=r"(a[0]), "=r"(a[1]), "=r"(a[2]), "=r"(a[3]) : "r"(addr));
}

static __device__ __forceinline__ void mma16816(float c[4], const uint32_t a[4],
                                                uint32_t b0, uint32_t b1) {
    asm volatile(
        "mma.sync.aligned.m16n8k16.row.col.f32.bf16.bf16.f32 "
        "{%0,%1,%2,%3}, {%4,%5,%6,%7}, {%8,%9}, {%0,%1,%2,%3};"
        : "+f"(c[0]), "+f"(c[1]), "+f"(c[2]), "+f"(c[3])
        : "r"(a[0]), "r"(a[1]), "r"(a[2]), "r"(a[3]), "r"(b0), "r"(b1));
}

__global__ void __launch_bounds__(TPB, 1) KroneNet_59485297049802_kernel(
    const float* __restrict__ x,
    const float* __restrict__ w1a, const float* __restrict__ w1b,
    const float* __restrict__ b1a, const float* __restrict__ b1b,
    const float* __restrict__ w2a, const float* __restrict__ w2b,
    const float* __restrict__ b2a, const float* __restrict__ b2b,
    const float* __restrict__ w3a, const float* __restrict__ w3b,
    const float* __restrict__ b3a, const float* __restrict__ b3b,
    float* __restrict__ out, int Bn)
{
    extern __shared__ __align__(16) char sm[];
    const uint32_t smb = smem_u32(sm);
    const int tid  = threadIdx.x;
    const int wid  = tid >> 5;
    const int lane = tid & 31;
    const int quad = lane >> 2;    // 0..7  (row group within fragment)
    const int qlid = lane & 3;     // 0..3  (column pair within fragment)

    float* pA = reinterpret_cast<float*>(sm + PA_OFF);
    float* pB = reinterpret_cast<float*>(sm + PB_OFF);

    // ---- persistent B fragments: W2 (row-major [n][k]) -> bf16 mma B operand ----
    // warp w owns columns n in [16w, 16w+16): j in {0,1} selects 8-col n-tile.
    // b0 = {W2[n][k0], W2[n][k0+1]}, b1 = same at k0+8;  n = 16w+8j+quad, k0 = 16kk+2*qlid
    uint32_t BfA[2][8][2], BfB[2][8][2];
    #pragma unroll
    for (int j = 0; j < 2; ++j) {
        const int n = 16 * wid + 8 * j + quad;
        #pragma unroll
        for (int kk = 0; kk < 8; ++kk) {
            const int k0 = 16 * kk + 2 * qlid;
            float2 lo = *reinterpret_cast<const float2*>(w2a + n * 128 + k0);
            float2 hi = *reinterpret_cast<const float2*>(w2a + n * 128 + k0 + 8);
            BfA[j][kk][0] = pack_bf16(lo.x, lo.y);
            BfA[j][kk][1] = pack_bf16(hi.x, hi.y);
            lo = *reinterpret_cast<const float2*>(w2b + n * 128 + k0);
            hi = *reinterpret_cast<const float2*>(w2b + n * 128 + k0 + 8);
            BfB[j][kk][0] = pack_bf16(lo.x, lo.y);
            BfB[j][kk][1] = pack_bf16(hi.x, hi.y);
        }
    }

    // ---- persistent epilogue constants for the columns this thread's D holds ----
    // D fragment cols: n = 16w + 8j + 2*qlid + h, h in {0,1}
    float baC[2][2], waC[2][2], bbC[2][2], wbC[3][2][2];
    #pragma unroll
    for (int j = 0; j < 2; ++j)
        #pragma unroll
        for (int h = 0; h < 2; ++h) {
            const int n = 16 * wid + 8 * j + 2 * qlid + h;
            baC[j][h] = b2a[n];
            waC[j][h] = w3a[n];
            bbC[j][h] = b2b[n];
            wbC[0][j][h] = w3b[n];
            wbC[1][j][h] = w3b[128 + n];
            wbC[2][j][h] = w3b[256 + n];
        }
    const float s_b3a = b3a[0];
    const float s_b3b0 = b3b[0], s_b3b1 = b3b[1], s_b3b2 = b3b[2];

    // ---- per-lane layer-1 weights: lane l owns k in {2l, 2l+1, 64+2l, 65+2l} ----
    float A0[4], A1[4], Ab[4], Bw0[4], Bw1[4], Bb[4];
    #pragma unroll
    for (int jj = 0; jj < 4; ++jj) {
        const int k = ((jj >> 1) << 6) + 2 * lane + (jj & 1);
        A0[jj]  = w1a[2 * k]; A1[jj]  = w1a[2 * k + 1]; Ab[jj] = b1a[k];
        Bw0[jj] = w1b[2 * k]; Bw1[jj] = w1b[2 * k + 1]; Bb[jj] = b1b[k];
    }

    // ldmatrix per-lane source address offset within an (i, kk) block:
    // lane L -> matrix m = L>>3; row += (m&1)*8; col-bytes += (m>>1)*16
    const uint32_t lrow  = (uint32_t)((lane & 7) + ((lane >> 3) & 1) * 8);
    const uint32_t lcolb = (uint32_t)(((lane >> 4) & 1) * 16);
    const uint32_t aA = smb + H1A_OFF + lrow * H1_STRIDE + lcolb;
    const uint32_t aB = smb + H1B_OFF + lrow * H1_STRIDE + lcolb;

    const int ntiles = Bn >> 7;
    const float2* x2 = reinterpret_cast<const float2*>(x);

    for (int t = blockIdx.x; t < ntiles; t += gridDim.x) {
        // ---- layer 1: h1 = relu(W1 x + b1) -> bf16 SMEM (warp w: rows 16w..16w+15) ----
        #pragma unroll 4
        for (int r = 0; r < 16; ++r) {
            const int row = wid * 16 + r;
            const int rg  = t * 128 + row;
            const float2 xa = x2[rg];
            const float2 xb = x2[Bn + rg];
            float ha[4], hb[4];
            #pragma unroll
            for (int jj = 0; jj < 4; ++jj) {
                ha[jj] = fmaxf(fmaf(xa.x, A0[jj],  fmaf(xa.y, A1[jj],  Ab[jj])), 0.f);
                hb[jj] = fmaxf(fmaf(xb.x, Bw0[jj], fmaf(xb.y, Bw1[jj], Bb[jj])), 0.f);
            }
            char* rowa = sm + H1A_OFF + row * H1_STRIDE;
            char* rowb = sm + H1B_OFF + row * H1_STRIDE;
            *reinterpret_cast<uint32_t*>(rowa + 4 * lane)       = pack_bf16(ha[0], ha[1]);
            *reinterpret_cast<uint32_t*>(rowa + 128 + 4 * lane) = pack_bf16(ha[2], ha[3]);
            *reinterpret_cast<uint32_t*>(rowb + 4 * lane)       = pack_bf16(hb[0], hb[1]);
            *reinterpret_cast<uint32_t*>(rowb + 128 + 4 * lane) = pack_bf16(hb[2], hb[3]);
        }
        __syncthreads();

        // ---- layer 2 (HMMA) + in-register epilogue, per m-tile of 16 rows ----
        #pragma unroll
        for (int i = 0; i < 8; ++i) {
            const uint32_t ibaseA = aA + (uint32_t)(i * 16 * H1_STRIDE);
            const uint32_t ibaseB = aB + (uint32_t)(i * 16 * H1_STRIDE);

            // ---- stream a ----
            {
                float c0[4] = {0.f, 0.f, 0.f, 0.f};
                float c1[4] = {0.f, 0.f, 0.f, 0.f};
                #pragma unroll
                for (int kk = 0; kk < 8; ++kk) {
                    uint32_t af[4];
                    ldsm_x4(af, ibaseA + 32u * kk);
                    mma16816(c0, af, BfA[0][kk][0], BfA[0][kk][1]);
                    mma16816(c1, af, BfA[1][kk][0], BfA[1][kk][1]);
                }
                float p0 = fmaxf(c0[0] + baC[0][0], 0.f) * waC[0][0]
                         + fmaxf(c0[1] + baC[0][1], 0.f) * waC[0][1]
                         + fmaxf(c1[0] + baC[1][0], 0.f) * waC[1][0]
                         + fmaxf(c1[1] + baC[1][1], 0.f) * waC[1][1];
                float p1 = fmaxf(c0[2] + baC[0][0], 0.f) * waC[0][0]
                         + fmaxf(c0[3] + baC[0][1], 0.f) * waC[0][1]
                         + fmaxf(c1[2] + baC[1][0], 0.f) * waC[1][0]
                         + fmaxf(c1[3] + baC[1][1], 0.f) * waC[1][1];
                p0 += __shfl_xor_sync(0xFFFFFFFFu, p0, 1);
                p0 += __shfl_xor_sync(0xFFFFFFFFu, p0, 2);
                p1 += __shfl_xor_sync(0xFFFFFFFFu, p1, 1);
                p1 += __shfl_xor_sync(0xFFFFFFFFu, p1, 2);
                if (qlid == 0) {
                    pA[wid * 128 + 16 * i + quad]     = p0;
                    pA[wid * 128 + 16 * i + quad + 8] = p1;
                }
            }

            // ---- stream b (3 output channels) ----
            {
                float c0[4] = {0.f, 0.f, 0.f, 0.f};
                float c1[4] = {0.f, 0.f, 0.f, 0.f};
                #pragma unroll
                for (int kk = 0; kk < 8; ++kk) {
                    uint32_t af[4];
                    ldsm_x4(af, ibaseB + 32u * kk);
                    mma16816(c0, af, BfB[0][kk][0], BfB[0][kk][1]);
                    mma16816(c1, af, BfB[1][kk][0], BfB[1][kk][1]);
                }
                const float v00 = fmaxf(c0[0] + bbC[0][0], 0.f);
                const float v01 = fmaxf(c0[1] + bbC[0][1], 0.f);
                const float v10 = fmaxf(c1[0] + bbC[1][0], 0.f);
                const float v11 = fmaxf(c1[1] + bbC[1][1], 0.f);
                const float u00 = fmaxf(c0[2] + bbC[0][0], 0.f);
                const float u01 = fmaxf(c0[3] + bbC[0][1], 0.f);
                const float u10 = fmaxf(c1[2] + bbC[1][0], 0.f);
                const float u11 = fmaxf(c1[3] + bbC[1][1], 0.f);
                #pragma unroll
                for (int c = 0; c < 3; ++c) {
                    float p0 = v00 * wbC[c][0][0] + v01 * wbC[c][0][1]
                             + v10 * wbC[c][1][0] + v11 * wbC[c][1][1];
                    float p1 = u00 * wbC[c][0][0] + u01 * wbC[c][0][1]
                             + u10 * wbC[c][1][0] + u11 * wbC[c][1][1];
                    p0 += __shfl_xor_sync(0xFFFFFFFFu, p0, 1);
                    p0 += __shfl_xor_sync(0xFFFFFFFFu, p0, 2);
                    p1 += __shfl_xor_sync(0xFFFFFFFFu, p1, 1);
                    p1 += __shfl_xor_sync(0xFFFFFFFFu, p1, 2);
                    if (qlid == 0) {
                        pB[wid * 384 + c * 128 + 16 * i + quad]     = p0;
                        pB[wid * 384 + c * 128 + 16 * i + quad + 8] = p1;
                    }
                }
            }
        }
        __syncthreads();

        // ---- final: combine warp partials, softmax, store ----
        if (tid < 128) {
            const int row = tid;
            float oa = s_b3a;
            float o0 = s_b3b0, o1 = s_b3b1, o2 = s_b3b2;
            #pragma unroll
            for (int w = 0; w < 8; ++w) {
                oa += pA[w * 128 + row];
                o0 += pB[w * 384 + row];
                o1 += pB[w * 384 + 128 + row];
                o2 += pB[w * 384 + 256 + row];
            }
            const float t0 = oa * o0, t1 = oa * o1, t2 = oa * o2;
            const float mx = fmaxf(t0, fmaxf(t1, t2));
            const float e0 = expf(t0 - mx), e1 = expf(t1 - mx), e2 = expf(t2 - mx);
            const float inv = 1.f / (e0 + e1 + e2);
            const int rg = t * 128 + row;
            out[rg * 3 + 0] = e0 * inv;
            out[rg * 3 + 1] = e1 * inv;
            out[rg * 3 + 2] = e2 * inv;
        }
        // next-tile partial writes are separated from these reads by the
        // h1 __syncthreads at the top of the next iteration.
    }
}

extern "C" void kernel_launch(void* const* d_in, const int* in_sizes, int n_in,
                              void* d_out, int out_size) {
    const float* x   = (const float*)d_in[0];
    const float* w1a = (const float*)d_in[1];
    const float* w1b = (const float*)d_in[2];
    const float* b1a = (const float*)d_in[3];
    const float* b1b = (const float*)d_in[4];
    const float* w2a = (const float*)d_in[5];
    const float* w2b = (const float*)d_in[6];
    const float* b2a = (const float*)d_in[7];
    const float* b2b = (const float*)d_in[8];
    const float* w3a = (const float*)d_in[9];
    const float* w3b = (const float*)d_in[10];
    const float* b3a = (const float*)d_in[11];
    const float* b3b = (const float*)d_in[12];
    float* out = (float*)d_out;

    int Bn = in_sizes[0] / 4;   // x is (2, B, 2) fp32

    cudaFuncSetAttribute(KroneNet_59485297049802_kernel,
                         cudaFuncAttributeMaxDynamicSharedMemorySize, SMEM_TOTAL);
    KroneNet_59485297049802_kernel<<<GRID, TPB, SMEM_TOTAL>>>(
        x, w1a, w1b, b1a, b1b, w2a, w2b, b2a, b2b, w3a, w3b, b3a, b3b, out, Bn);
}